// round 10
// baseline (speedup 1.0000x reference)
#include <cuda_runtime.h>
#include <cuda_bf16.h>
#include <cstdint>

// Problem shape (fixed by the dataset)
#define B_ 8
#define T_ 4096
#define F_ 512
#define ROWS_ (B_ * T_)

#define BLK_  1024
#define MAXGRID_ 512

// Scratch (no allocations allowed) — device globals.
__device__ float g_z[ROWS_];        // linear scores (monotone-equiv. for peaks)
__device__ int   g_idx[ROWS_];      // per batch: compact list of peak t's (stable order)
__device__ int   g_hlens[B_];       // peak counts per batch
__device__ unsigned g_cnt[B_];      // rows of batch b finished (GEMV+zero)
__device__ unsigned g_flag[B_];     // scan of batch b published
__device__ unsigned g_finish = 0;   // completion counter (reset protocol)

__global__ void __launch_bounds__(BLK_, 1)
k_fused(const float* __restrict__ feat, const float* __restrict__ W,
        float* __restrict__ out, int out_size) {
    const int tid  = threadIdx.x;
    const int lane = tid & 31;
    const int wid  = tid >> 5;                 // 0..31
    const int bid  = blockIdx.x;
    const int grid = gridDim.x;

    __shared__ int warp_sums[32];
    __shared__ int warp_incl[32];

    // ------------------------------------------------------------------
    // Phase 1: each CTA owns a CONTIGUOUS chunk of rows. GEMV reads +
    // unconditional zero-fill writes interleaved (R9 trick), 4 rows/warp.
    const int R  = (ROWS_ + grid - 1) / grid;
    const int cs = bid * R;
    const int ce = (cs + R < ROWS_) ? cs + R : ROWS_;
    {
        const float4* w4 = reinterpret_cast<const float4*>(W);
        float4 wreg[4];
#pragma unroll
        for (int i = 0; i < 4; i++) wreg[i] = w4[lane + i * 32];
        const float4 z4 = make_float4(0.f, 0.f, 0.f, 0.f);

        for (int r0 = cs + wid * 4; r0 < ce; r0 += 32 * 4) {
            const int nr = (ce - r0 < 4) ? (ce - r0) : 4;

            float4 a[4][4];
#pragma unroll
            for (int k = 0; k < 4; k++) {
                if (k < nr) {
                    const float4* f = reinterpret_cast<const float4*>(feat + (size_t)(r0 + k) * F_);
#pragma unroll
                    for (int i = 0; i < 4; i++) a[k][i] = f[lane + i * 32];
                }
            }
            // Zero-fill the same output rows while loads are in flight.
#pragma unroll
            for (int k = 0; k < 4; k++) {
                if (k < nr) {
                    float4* d = reinterpret_cast<float4*>(out + (size_t)(r0 + k) * F_);
#pragma unroll
                    for (int i = 0; i < 4; i++) __stcs(&d[lane + i * 32], z4);
                }
            }
            float s[4] = {0.f, 0.f, 0.f, 0.f};
#pragma unroll
            for (int i = 0; i < 4; i++) {
                const float4 w = wreg[i];
#pragma unroll
                for (int k = 0; k < 4; k++)
                    s[k] += a[k][i].x * w.x + a[k][i].y * w.y + a[k][i].z * w.z + a[k][i].w * w.w;
            }
#pragma unroll
            for (int o = 16; o > 0; o >>= 1) {
#pragma unroll
                for (int k = 0; k < 4; k++)
                    s[k] += __shfl_down_sync(0xFFFFFFFFu, s[k], o);
            }
            if (lane == 0) {
#pragma unroll
                for (int k = 0; k < 4; k++)
                    if (k < nr) g_z[r0 + k] = s[k];
            }
        }
    }
    __syncthreads();
    if (tid == 0 && cs < ce) {
        __threadfence();                        // publish z + zero-fill
        const int b0 = cs >> 12, b1 = (ce - 1) >> 12;   // T_ = 4096
        for (int b = b0; b <= b1; b++) {
            const int lo = (cs > b * T_) ? cs : b * T_;
            const int hi = (ce < (b + 1) * T_) ? ce : (b + 1) * T_;
            atomicAdd(&g_cnt[b], (unsigned)(hi - lo));
        }
    }

    // ------------------------------------------------------------------
    // Phase 2: CTA b (b<8) scans batch b as soon as its z rows are ready.
    if (bid < B_) {
        const int b = bid;
        if (tid == 0) {
            while (atomicAdd(&g_cnt[b], 0u) < (unsigned)T_) __nanosleep(100);
            __threadfence();                    // acquire producers' z
        }
        __syncthreads();

        const float* zb = g_z + b * T_;
        const int t0 = tid * 4;                 // 1024 threads * 4 = 4096

        int flags[4];
        int cnt = 0;
#pragma unroll
        for (int k = 0; k < 4; k++) {
            int t = t0 + k;
            float c = zb[t];
            float l = (t > 0)      ? zb[t - 1] : c;
            float r = (t < T_ - 1) ? zb[t + 1] : c;
            flags[k] = (c >= l) & (c >= r);
            cnt += flags[k];
        }
        int v = cnt;
#pragma unroll
        for (int o = 1; o < 32; o <<= 1) {
            int n = __shfl_up_sync(0xFFFFFFFFu, v, o);
            if (lane >= o) v += n;
        }
        if (lane == 31) warp_sums[wid] = v;
        __syncthreads();
        if (wid == 0) {
            int s = warp_sums[lane];
#pragma unroll
            for (int o = 1; o < 32; o <<= 1) {
                int n = __shfl_up_sync(0xFFFFFFFFu, s, o);
                if (lane >= o) s += n;
            }
            warp_incl[lane] = s;
        }
        __syncthreads();

        int excl = (v - cnt) + (wid > 0 ? warp_incl[wid - 1] : 0);
#pragma unroll
        for (int k = 0; k < 4; k++) {
            int t = t0 + k;
            if (flags[k]) g_idx[b * T_ + excl] = t;   // compact gather list
            excl += flags[k];
        }
        if (tid == 0) {
            int hl = warp_incl[31];
            g_hlens[b] = hl;
            if (out_size >= ROWS_ * F_ + B_)
                out[(size_t)ROWS_ * F_ + b] = (float)hl;
        }
        __syncthreads();
        if (tid == 0) {
            __threadfence();                    // publish idx/hlens
            atomicExch(&g_flag[b], 1u);
        }
    }

    // ------------------------------------------------------------------
    // Phase 3: gather-copy peak rows, batch by batch as flags land.
    // Contiguous coalesced writes; reads are L2-resident feat rows.
    {
        const int sub = tid >> 7;               // 0..7: group of 128 threads
        const int j   = tid & 127;              // float4 index within row

        for (int b = 0; b < B_; b++) {
            if (tid == 0) {
                while (atomicAdd(&g_flag[b], 0u) == 0u) __nanosleep(100);
                __threadfence();                // acquire idx/hlens
            }
            __syncthreads();
            const int hl = g_hlens[b];
            const size_t bbase = (size_t)b * T_;

            for (int i = bid * 8 + sub; i < hl; i += grid * 8) {
                const int t = g_idx[b * T_ + i];
                const float4 v = reinterpret_cast<const float4*>(feat + (bbase + t) * F_)[j];
                __stcs(&reinterpret_cast<float4*>(out + (bbase + i) * F_)[j], v);
            }
        }
    }

    // ------------------------------------------------------------------
    // Reset for next graph replay: last CTA to finish clears the flags.
    __syncthreads();
    if (tid == 0) {
        __threadfence();
        unsigned f = atomicAdd(&g_finish, 1u);
        if (f == (unsigned)grid - 1u) {
#pragma unroll
            for (int i = 0; i < B_; i++) { g_cnt[i] = 0u; g_flag[i] = 0u; }
            g_finish = 0u;
            __threadfence();
        }
    }
}

extern "C" void kernel_launch(void* const* d_in, const int* in_sizes, int n_in,
                              void* d_out, int out_size) {
    const float* feat = (const float*)d_in[0];
    const float* W    = (const float*)d_in[1];
    float* out        = (float*)d_out;

    int sm = 148;
    cudaDeviceGetAttribute(&sm, cudaDevAttrMultiProcessorCount, 0);
    if (sm < B_) sm = B_;
    if (sm > MAXGRID_) sm = MAXGRID_;

    k_fused<<<sm, BLK_>>>(feat, W, out, out_size);
}

// round 11
// speedup vs baseline: 1.9125x; 1.9125x over previous
#include <cuda_runtime.h>
#include <cuda_bf16.h>
#include <cstdint>

// Problem shape (fixed by the dataset)
#define B_ 8
#define T_ 4096
#define F_ 512
#define ROWS_ (B_ * T_)

#define GRID_ 148          // 1 CTA per SM; all co-resident
#define BLK_  1024

// Scratch (no allocations allowed) — device globals.
__device__ float g_z[ROWS_];        // linear scores (monotone-equiv. for peaks)
__device__ int   g_idx[ROWS_];      // per batch: compact list of peak t's (stable order)
__device__ int   g_hlens[B_];       // peak counts per batch
__device__ unsigned g_bar_count = 0;
__device__ unsigned g_bar_gen   = 0;

// Software grid barrier (all 148 CTAs co-resident at 1 CTA/SM).
__device__ __forceinline__ void grid_barrier() {
    __syncthreads();
    if (threadIdx.x == 0) {
        unsigned gen = *(volatile unsigned*)&g_bar_gen;
        __threadfence();                       // publish this block's phase writes
        unsigned arr = atomicAdd(&g_bar_count, 1u);
        if (arr == GRID_ - 1) {
            atomicExch(&g_bar_count, 0u);
            __threadfence();
            atomicAdd(&g_bar_gen, 1u);         // release
        } else {
            while (*(volatile unsigned*)&g_bar_gen == gen) { }
        }
        __threadfence();                       // acquire other blocks' writes
    }
    __syncthreads();
}

__global__ void __launch_bounds__(BLK_, 1)
k_fused(const float* __restrict__ feat, const float* __restrict__ W,
        float* __restrict__ out, int out_size) {
    const int tid  = threadIdx.x;
    const int lane = tid & 31;
    const int wid  = tid >> 5;                 // 0..31
    const int bid  = blockIdx.x;

    __shared__ int warp_sums[32];
    __shared__ int warp_incl[32];
    __shared__ int s_hl[B_];

    // ------------------------------------------------------------------
    // Phase 1: pure GEMV. FOUR rows per warp per iteration:
    // 16 independent LDG.128 in flight, 4 independent reduce chains.
    {
        const float4* w4 = reinterpret_cast<const float4*>(W);
        float4 wreg[4];
#pragma unroll
        for (int i = 0; i < 4; i++) wreg[i] = w4[lane + i * 32];

        for (int row0 = bid * 128 + wid * 4; row0 < ROWS_; row0 += GRID_ * 128) {
            const float4* f0 = reinterpret_cast<const float4*>(feat + (size_t)(row0 + 0) * F_);
            const float4* f1 = reinterpret_cast<const float4*>(feat + (size_t)(row0 + 1) * F_);
            const float4* f2 = reinterpret_cast<const float4*>(feat + (size_t)(row0 + 2) * F_);
            const float4* f3 = reinterpret_cast<const float4*>(feat + (size_t)(row0 + 3) * F_);
            float s0 = 0.f, s1 = 0.f, s2 = 0.f, s3 = 0.f;
#pragma unroll
            for (int i = 0; i < 4; i++) {
                const int idx = lane + i * 32;
                const float4 w = wreg[i];
                float4 a0 = f0[idx];
                float4 a1 = f1[idx];
                float4 a2 = f2[idx];
                float4 a3 = f3[idx];
                s0 += a0.x * w.x + a0.y * w.y + a0.z * w.z + a0.w * w.w;
                s1 += a1.x * w.x + a1.y * w.y + a1.z * w.z + a1.w * w.w;
                s2 += a2.x * w.x + a2.y * w.y + a2.z * w.z + a2.w * w.w;
                s3 += a3.x * w.x + a3.y * w.y + a3.z * w.z + a3.w * w.w;
            }
#pragma unroll
            for (int o = 16; o > 0; o >>= 1) {
                s0 += __shfl_down_sync(0xFFFFFFFFu, s0, o);
                s1 += __shfl_down_sync(0xFFFFFFFFu, s1, o);
                s2 += __shfl_down_sync(0xFFFFFFFFu, s2, o);
                s3 += __shfl_down_sync(0xFFFFFFFFu, s3, o);
            }
            if (lane == 0) {
                g_z[row0 + 0] = s0;
                g_z[row0 + 1] = s1;
                g_z[row0 + 2] = s2;
                g_z[row0 + 3] = s3;
            }
        }
    }

    grid_barrier();

    // ------------------------------------------------------------------
    // Phase 2: blocks 0..7 — peak detect + compact gather list per batch.
    if (bid < B_) {
        const int b = bid;
        const float* zb = g_z + b * T_;
        const int t0 = tid * 4;                // 1024 threads * 4 = 4096

        int flags[4];
        int cnt = 0;
#pragma unroll
        for (int k = 0; k < 4; k++) {
            int t = t0 + k;
            float c = zb[t];
            float l = (t > 0)      ? zb[t - 1] : c;
            float r = (t < T_ - 1) ? zb[t + 1] : c;
            flags[k] = (c >= l) & (c >= r);
            cnt += flags[k];
        }

        int v = cnt;
#pragma unroll
        for (int o = 1; o < 32; o <<= 1) {
            int n = __shfl_up_sync(0xFFFFFFFFu, v, o);
            if (lane >= o) v += n;
        }
        if (lane == 31) warp_sums[wid] = v;
        __syncthreads();
        if (wid == 0) {
            int s = warp_sums[lane];
#pragma unroll
            for (int o = 1; o < 32; o <<= 1) {
                int n = __shfl_up_sync(0xFFFFFFFFu, s, o);
                if (lane >= o) s += n;
            }
            warp_incl[lane] = s;
        }
        __syncthreads();

        int excl = (v - cnt) + (wid > 0 ? warp_incl[wid - 1] : 0);
#pragma unroll
        for (int k = 0; k < 4; k++) {
            int t = t0 + k;
            if (flags[k]) g_idx[b * T_ + excl] = t;   // compact: i-th peak is t
            excl += flags[k];
        }
        if (tid == 0) {
            int hl = warp_incl[31];
            g_hlens[b] = hl;
            if (out_size >= ROWS_ * F_ + B_)
                out[(size_t)ROWS_ * F_ + b] = (float)hl;
        }
    }

    grid_barrier();

    // ------------------------------------------------------------------
    // Phase 3: destination-centric writer. Each output row (b, i) written
    // exactly once: i < hl[b] -> copy feat row g_idx[b][i] (L2-resident),
    // else zero. Perfectly coalesced sequential writes, no scatter.
    // 1024 threads = 8 groups of 128; each group does 4 dest rows/iter.
    {
        if (tid < B_) s_hl[tid] = g_hlens[tid];
        __syncthreads();

        const int sub = tid >> 7;              // 0..7: group id
        const int j   = tid & 127;             // float4 index within row
        const float4 z4 = make_float4(0.f, 0.f, 0.f, 0.f);

        for (int base = bid * 32 + sub * 4; base < ROWS_; base += GRID_ * 32) {
            // 4 destination rows base..base+3 (all same batch except at
            // 4096-boundaries, handled per-row below).
            int src[4];
#pragma unroll
            for (int k = 0; k < 4; k++) {
                const int row = base + k;
                const int b = row >> 12;       // T_ = 4096
                const int i = row & (T_ - 1);
                src[k] = (i < s_hl[b]) ? (b * T_ + g_idx[row]) : -1;
            }
            float4 v4[4];
#pragma unroll
            for (int k = 0; k < 4; k++)
                v4[k] = (src[k] >= 0)
                    ? reinterpret_cast<const float4*>(feat + (size_t)src[k] * F_)[j]
                    : z4;
#pragma unroll
            for (int k = 0; k < 4; k++)
                __stcs(&reinterpret_cast<float4*>(out + (size_t)(base + k) * F_)[j], v4[k]);
        }
    }
}

extern "C" void kernel_launch(void* const* d_in, const int* in_sizes, int n_in,
                              void* d_out, int out_size) {
    const float* feat = (const float*)d_in[0];
    const float* W    = (const float*)d_in[1];
    float* out        = (float*)d_out;
    k_fused<<<GRID_, BLK_>>>(feat, W, out, out_size);
}

// round 12
// speedup vs baseline: 1.9262x; 1.0072x over previous
#include <cuda_runtime.h>
#include <cuda_bf16.h>
#include <cstdint>

// Problem shape (fixed by the dataset)
#define B_ 8
#define T_ 4096
#define F_ 512
#define ROWS_ (B_ * T_)

#define GRID_ 148          // 1 CTA per SM; all co-resident
#define BLK_  1024

#define TILE_ROWS 32
#define NT (ROWS_ / TILE_ROWS)          // 1024 tiles
#define TILE_F4 (TILE_ROWS * F_ / 4)    // 4096 float4 per tile
#define SMEM_BYTES (2 * TILE_ROWS * F_ * 4)   // 128 KB double buffer

// Scratch (no allocations allowed) — device globals.
__device__ float g_z[ROWS_];        // linear scores (monotone-equiv. for peaks)
__device__ int   g_idx[ROWS_];      // per batch: compact list of peak t's (stable order)
__device__ int   g_hlens[B_];       // peak counts per batch
__device__ unsigned g_bar_count = 0;
__device__ unsigned g_bar_gen   = 0;

// Software grid barrier (all 148 CTAs co-resident at 1 CTA/SM).
__device__ __forceinline__ void grid_barrier() {
    __syncthreads();
    if (threadIdx.x == 0) {
        unsigned gen = *(volatile unsigned*)&g_bar_gen;
        __threadfence();
        unsigned arr = atomicAdd(&g_bar_count, 1u);
        if (arr == GRID_ - 1) {
            atomicExch(&g_bar_count, 0u);
            __threadfence();
            atomicAdd(&g_bar_gen, 1u);
        } else {
            while (*(volatile unsigned*)&g_bar_gen == gen) { }
        }
        __threadfence();
    }
    __syncthreads();
}

__device__ __forceinline__ uint32_t smem_u32(const void* p) {
    uint32_t a;
    asm("{ .reg .u64 t; cvta.to.shared.u64 t, %1; cvt.u32.u64 %0, t; }"
        : "=r"(a) : "l"(p));
    return a;
}

__global__ void __launch_bounds__(BLK_, 1)
k_fused(const float* __restrict__ feat, const float* __restrict__ W,
        float* __restrict__ out, int out_size) {
    extern __shared__ float dynsmem[];          // 2 x 32 x 512 floats
    const int tid  = threadIdx.x;
    const int lane = tid & 31;
    const int wid  = tid >> 5;                  // 0..31
    const int bid  = blockIdx.x;

    __shared__ int warp_sums[32];
    __shared__ int warp_incl[32];
    __shared__ int s_hl[B_];

    // ------------------------------------------------------------------
    // Phase 1: GEMV via cp.async double-buffered smem pipeline.
    // Each tile: 32 rows (64 KB). Warps compute one row each from smem.
    {
        const float4* w4 = reinterpret_cast<const float4*>(W);
        float4 wreg[4];
#pragma unroll
        for (int i = 0; i < 4; i++) wreg[i] = w4[lane + i * 32];

        const uint32_t sbase = smem_u32(dynsmem);
        const float4* featv = reinterpret_cast<const float4*>(feat);

        // prefetch first tile into buffer 0
        {
            const int t0 = bid;                 // bid < 148 < NT always
#pragma unroll
            for (int k = 0; k < 4; k++) {
                const int fi = tid + k * 1024;  // float4 index within tile
                const float4* g = featv + (size_t)t0 * TILE_F4 + fi;
                const uint32_t dst = sbase + (uint32_t)fi * 16u;
                asm volatile("cp.async.cg.shared.global [%0], [%1], 16;"
                             :: "r"(dst), "l"(g));
            }
            asm volatile("cp.async.commit_group;");
        }

        int pb = 0;
        for (int t = bid; t < NT; t += GRID_) {
            const int tn = t + GRID_;
            if (tn < NT) {
                const uint32_t bofs = (uint32_t)(pb ^ 1) * (TILE_F4 * 16u);
#pragma unroll
                for (int k = 0; k < 4; k++) {
                    const int fi = tid + k * 1024;
                    const float4* g = featv + (size_t)tn * TILE_F4 + fi;
                    const uint32_t dst = sbase + bofs + (uint32_t)fi * 16u;
                    asm volatile("cp.async.cg.shared.global [%0], [%1], 16;"
                                 :: "r"(dst), "l"(g));
                }
                asm volatile("cp.async.commit_group;");
                asm volatile("cp.async.wait_group 1;");   // tile t complete
            } else {
                asm volatile("cp.async.wait_group 0;");
            }
            __syncthreads();

            // compute: warp wid handles row wid of tile t
            const float4* rp = reinterpret_cast<const float4*>(
                dynsmem + (size_t)pb * (TILE_F4 * 4) + (size_t)wid * F_);
            float s = 0.f;
#pragma unroll
            for (int i = 0; i < 4; i++) {
                const float4 a = rp[lane + i * 32];
                const float4 w = wreg[i];
                s += a.x * w.x + a.y * w.y + a.z * w.z + a.w * w.w;
            }
#pragma unroll
            for (int o = 16; o > 0; o >>= 1)
                s += __shfl_down_sync(0xFFFFFFFFu, s, o);
            if (lane == 0) g_z[t * TILE_ROWS + wid] = s;

            __syncthreads();                    // buffer pb safe to overwrite
            pb ^= 1;
        }
    }

    grid_barrier();

    // ------------------------------------------------------------------
    // Phase 2: blocks 0..7 — peak detect + compact gather list per batch.
    if (bid < B_) {
        const int b = bid;
        const float* zb = g_z + b * T_;
        const int t0 = tid * 4;                 // 1024 threads * 4 = 4096

        int flags[4];
        int cnt = 0;
#pragma unroll
        for (int k = 0; k < 4; k++) {
            int t = t0 + k;
            float c = zb[t];
            float l = (t > 0)      ? zb[t - 1] : c;
            float r = (t < T_ - 1) ? zb[t + 1] : c;
            flags[k] = (c >= l) & (c >= r);
            cnt += flags[k];
        }

        int v = cnt;
#pragma unroll
        for (int o = 1; o < 32; o <<= 1) {
            int n = __shfl_up_sync(0xFFFFFFFFu, v, o);
            if (lane >= o) v += n;
        }
        if (lane == 31) warp_sums[wid] = v;
        __syncthreads();
        if (wid == 0) {
            int s = warp_sums[lane];
#pragma unroll
            for (int o = 1; o < 32; o <<= 1) {
                int n = __shfl_up_sync(0xFFFFFFFFu, s, o);
                if (lane >= o) s += n;
            }
            warp_incl[lane] = s;
        }
        __syncthreads();

        int excl = (v - cnt) + (wid > 0 ? warp_incl[wid - 1] : 0);
#pragma unroll
        for (int k = 0; k < 4; k++) {
            int t = t0 + k;
            if (flags[k]) g_idx[b * T_ + excl] = t;
            excl += flags[k];
        }
        if (tid == 0) {
            int hl = warp_incl[31];
            g_hlens[b] = hl;
            if (out_size >= ROWS_ * F_ + B_)
                out[(size_t)ROWS_ * F_ + b] = (float)hl;
        }
    }

    grid_barrier();

    // ------------------------------------------------------------------
    // Phase 3: destination-centric writer (R11). Each output row (b, i)
    // written exactly once: i < hl[b] -> copy feat row g_idx[b][i]
    // (L2-resident), else zero. Coalesced sequential writes.
    {
        if (tid < B_) s_hl[tid] = g_hlens[tid];
        __syncthreads();

        const int sub = tid >> 7;               // 0..7: group of 128 threads
        const int j   = tid & 127;              // float4 index within row
        const float4 z4 = make_float4(0.f, 0.f, 0.f, 0.f);

        for (int base = bid * 32 + sub * 4; base < ROWS_; base += GRID_ * 32) {
            int src[4];
#pragma unroll
            for (int k = 0; k < 4; k++) {
                const int row = base + k;
                const int b = row >> 12;        // T_ = 4096
                const int i = row & (T_ - 1);
                src[k] = (i < s_hl[b]) ? (b * T_ + g_idx[row]) : -1;
            }
            float4 v4[4];
#pragma unroll
            for (int k = 0; k < 4; k++)
                v4[k] = (src[k] >= 0)
                    ? reinterpret_cast<const float4*>(feat + (size_t)src[k] * F_)[j]
                    : z4;
#pragma unroll
            for (int k = 0; k < 4; k++)
                __stcs(&reinterpret_cast<float4*>(out + (size_t)(base + k) * F_)[j], v4[k]);
        }
    }
}

extern "C" void kernel_launch(void* const* d_in, const int* in_sizes, int n_in,
                              void* d_out, int out_size) {
    const float* feat = (const float*)d_in[0];
    const float* W    = (const float*)d_in[1];
    float* out        = (float*)d_out;

    cudaFuncSetAttribute(k_fused, cudaFuncAttributeMaxDynamicSharedMemorySize,
                         SMEM_BYTES);
    k_fused<<<GRID_, BLK_, SMEM_BYTES>>>(feat, W, out, out_size);
}